// round 16
// baseline (speedup 1.0000x reference)
#include <cuda_runtime.h>
#include <cuda_bf16.h>
#include <cstdint>

#define D            128
#define S            16
#define BMAX         8192

// ---------------- scratch (device globals: allocation-free) ----------------
__device__ __nv_bfloat16 g_x0 [BMAX * D];  // msg + rep0 (bf16, GEMM A input)
__device__ __nv_bfloat16 g_msg[BMAX * D];  // msg (bf16, residual adds)
__device__ float         g_ue [BMAX * D];  // u embedding (fp32, epilogue dot)

__device__ __forceinline__ uint32_t pack_bf16x2(float lo, float hi) {
    __nv_bfloat162 v = __floats2bfloat162_rn(lo, hi);
    return *(uint32_t*)&v;
}

// ============================ kernel 1: gather =============================
// One warp per item, streaming blocks, 32 warps/SM -> measured ~HBM roofline.
__global__ __launch_bounds__(256, 4)
void gather_kernel(const int* __restrict__ u,
                   const int* __restrict__ v,
                   const int* __restrict__ adj_ent,
                   const int* __restrict__ adj_rel,
                   const float* __restrict__ usr,
                   const float* __restrict__ ent,
                   const float* __restrict__ rel,
                   int B)
{
    const int lane = threadIdx.x & 31;
    const int item = blockIdx.x * 8 + (threadIdx.x >> 5);
    if (item >= B) return;

    const float4* usr4 = (const float4*)usr;
    const float4* ent4 = (const float4*)ent;
    const float4* rel4 = (const float4*)rel;
    const int4*   adjE4 = (const int4*)adj_ent;
    const int4*   adjR4 = (const int4*)adj_rel;

    const int iu = u[item];
    const int iv = v[item];

    const float4 uex = usr4[(size_t)iu * 32 + lane];
    const float4 rp  = ent4[(size_t)iv * 32 + lane];

    // u embedding out (coalesced fp32) -- turns kernel2's random gather
    // into a streaming read
    ((float4*)(g_ue + item * D))[lane] = uex;

    int eix[S], rix[S];
    #pragma unroll
    for (int q = 0; q < 4; q++) {
        const int4 e = __ldg(&adjE4[iv * 4 + q]);
        const int4 r = __ldg(&adjR4[iv * 4 + q]);
        eix[q*4+0] = e.x; eix[q*4+1] = e.y; eix[q*4+2] = e.z; eix[q*4+3] = e.w;
        rix[q*4+0] = r.x; rix[q*4+1] = r.y; rix[q*4+2] = r.z; rix[q*4+3] = r.w;
    }

    // fused single-pass attention (scores tiny; no-max-sub exp validated)
    float sum = 0.f;
    float4 msg = make_float4(0.f, 0.f, 0.f, 0.f);
    #pragma unroll
    for (int s = 0; s < S; s++) {
        const float4 r4 = rel4[(size_t)rix[s] * 32 + lane];   // L1-resident table
        const float4 e4 = ent4[(size_t)eix[s] * 32 + lane];   // in flight with r4
        float p = uex.x * r4.x + uex.y * r4.y + uex.z * r4.z + uex.w * r4.w;
        #pragma unroll
        for (int o = 16; o > 0; o >>= 1)
            p += __shfl_xor_sync(0xffffffffu, p, o);
        const float es = __expf(p);
        sum += es;
        msg.x = fmaf(es, e4.x, msg.x);
        msg.y = fmaf(es, e4.y, msg.y);
        msg.z = fmaf(es, e4.z, msg.z);
        msg.w = fmaf(es, e4.w, msg.w);
    }
    const float inv = __frcp_rn(sum);
    msg.x *= inv; msg.y *= inv; msg.z *= inv; msg.w *= inv;

    // bf16 outputs (halves scratch traffic vs fp32)
    ((uint2*)(g_msg + item * D))[lane] =
        make_uint2(pack_bf16x2(msg.x, msg.y), pack_bf16x2(msg.z, msg.w));
    ((uint2*)(g_x0 + item * D))[lane] =
        make_uint2(pack_bf16x2(msg.x + rp.x, msg.y + rp.y),
                   pack_bf16x2(msg.z + rp.z, msg.w + rp.w));
}

// ====================== kernel 2: bf16 MMA GEMM + epilogue =================
#define WARPS_PB     16
#define ITEM_TILE    2
#define ITEMS_PB     32
#define BLOCK_THREADS 512
#define HSTRIDE      136
#define FSTRIDE      132

// smem: Wt bf16 [128][136]=34816 (reused as Hs fp32 [32][132]); Xs/Ms bf16 [32][136]
#define OFF_WT  0
#define OFF_XS  34816
#define OFF_MS  (34816 + 8704)
#define SMEM_BYTES (OFF_MS + 8704)      // 52224 -> 2 blocks/SM = 32 warps/SM

__device__ __forceinline__ void mma_bf16(float acc[4], const uint32_t a[4],
                                         const uint32_t b[2]) {
    asm("mma.sync.aligned.m16n8k16.row.col.f32.bf16.bf16.f32 "
        "{%0,%1,%2,%3}, {%4,%5,%6,%7}, {%8,%9}, {%0,%1,%2,%3};"
        : "+f"(acc[0]), "+f"(acc[1]), "+f"(acc[2]), "+f"(acc[3])
        : "r"(a[0]), "r"(a[1]), "r"(a[2]), "r"(a[3]),
          "r"(b[0]), "r"(b[1]));
}

__global__ __launch_bounds__(BLOCK_THREADS, 2)
void gemm_kernel(const float* __restrict__ W,
                 const float* __restrict__ bias,
                 float* __restrict__ out,
                 int B)
{
    extern __shared__ char sm[];
    __nv_bfloat16* Wt = (__nv_bfloat16*)(sm + OFF_WT);   // [n][k] transposed
    __nv_bfloat16* Xs = (__nv_bfloat16*)(sm + OFF_XS);
    __nv_bfloat16* Ms = (__nv_bfloat16*)(sm + OFF_MS);
    float*         Hs = (float*)        (sm + OFF_WT);   // epilogue reuse

    const int tid  = threadIdx.x;
    const int lane = tid & 31;
    const int wid  = tid >> 5;
    const int g    = lane >> 2;
    const int tq   = lane & 3;

    // ---- stage Wt transposed (bf16) ----
    for (int idx = tid; idx < D * D; idx += BLOCK_THREADS) {
        const int k = idx >> 7;
        const int n = idx & 127;
        Wt[n * HSTRIDE + k] = __float2bfloat16(W[idx]);
    }

    // ---- stage Xs/Ms from scratch (coalesced bf16: 8B/lane = 256B/row) ----
    const int base = blockIdx.x * ITEMS_PB;
    #pragma unroll
    for (int t = 0; t < ITEM_TILE; t++) {
        const int row = wid * ITEM_TILE + t;
        const int cit = min(base + row, B - 1);
        ((uint2*)(Xs + row * HSTRIDE))[lane] = ((const uint2*)(g_x0  + cit * D))[lane];
        ((uint2*)(Ms + row * HSTRIDE))[lane] = ((const uint2*)(g_msg + cit * D))[lane];
    }
    __syncthreads();

    // ---- main GEMM: 2 layers relu(x @ W + b); warp owns N=8 cols ----
    const int ncol0 = wid * 8;
    const float bb0 = __ldg(&bias[ncol0 + tq * 2]);
    const float bb1 = __ldg(&bias[ncol0 + tq * 2 + 1]);

    float acc[2][4];

    #pragma unroll
    for (int iter = 0; iter < 2; iter++) {
        #pragma unroll
        for (int mt = 0; mt < 2; mt++) {
            acc[mt][0] = bb0; acc[mt][1] = bb1;
            acc[mt][2] = bb0; acc[mt][3] = bb1;
        }

        #pragma unroll
        for (int kt = 0; kt < 8; kt++) {
            uint32_t b[2];
            const __nv_bfloat16* wb = Wt + (ncol0 + g) * HSTRIDE + kt * 16 + tq * 2;
            b[0] = *(const uint32_t*)(wb);
            b[1] = *(const uint32_t*)(wb + 8);
            #pragma unroll
            for (int mt = 0; mt < 2; mt++) {
                uint32_t a[4];
                const __nv_bfloat16* xb = Xs + (mt * 16 + g) * HSTRIDE + kt * 16 + tq * 2;
                a[0] = *(const uint32_t*)(xb);
                a[1] = *(const uint32_t*)(xb + 8 * HSTRIDE);
                a[2] = *(const uint32_t*)(xb + 8);
                a[3] = *(const uint32_t*)(xb + 8 * HSTRIDE + 8);
                mma_bf16(acc[mt], a, b);
            }
        }

        __syncthreads();

        if (iter == 0) {
            // x1 = msg + relu(h1): warp writes its own 8 cols for all 32 rows
            #pragma unroll
            for (int mt = 0; mt < 2; mt++) {
                const int c0 = ncol0 + tq * 2;
                const int r0 = mt * 16 + g;
                const int r1 = r0 + 8;
                const float2 m0 = __bfloat1622float2(*(const __nv_bfloat162*)(Ms + r0 * HSTRIDE + c0));
                const float2 m1 = __bfloat1622float2(*(const __nv_bfloat162*)(Ms + r1 * HSTRIDE + c0));
                *(uint32_t*)(Xs + r0 * HSTRIDE + c0) =
                    pack_bf16x2(m0.x + fmaxf(acc[mt][0], 0.f),
                                m0.y + fmaxf(acc[mt][1], 0.f));
                *(uint32_t*)(Xs + r1 * HSTRIDE + c0) =
                    pack_bf16x2(m1.x + fmaxf(acc[mt][2], 0.f),
                                m1.y + fmaxf(acc[mt][3], 0.f));
            }
            __syncthreads();
        }
    }

    // rep2 = relu(h2) -> Hs fp32 (Wt region; Wt reads done)
    #pragma unroll
    for (int mt = 0; mt < 2; mt++) {
        const int c0 = ncol0 + tq * 2;
        const int r0 = mt * 16 + g;
        const int r1 = r0 + 8;
        *(float2*)(Hs + r0 * FSTRIDE + c0) =
            make_float2(fmaxf(acc[mt][0], 0.f), fmaxf(acc[mt][1], 0.f));
        *(float2*)(Hs + r1 * FSTRIDE + c0) =
            make_float2(fmaxf(acc[mt][2], 0.f), fmaxf(acc[mt][3], 0.f));
    }
    __syncthreads();

    // ---- epilogue: sigmoid(dot(u_emb, rep2)); u_emb coalesced from scratch ----
    #pragma unroll
    for (int t = 0; t < ITEM_TILE; t++) {
        const int row  = wid * ITEM_TILE + t;
        const int item = base + row;
        const int cit  = min(item, B - 1);
        const float4 uex = ((const float4*)(g_ue + cit * D))[lane];
        const float4 h = *(const float4*)(Hs + row * FSTRIDE + lane * 4);
        float p = uex.x * h.x + uex.y * h.y + uex.z * h.z + uex.w * h.w;
        #pragma unroll
        for (int o = 16; o > 0; o >>= 1)
            p += __shfl_xor_sync(0xffffffffu, p, o);
        if (lane == 0 && item < B)
            out[item] = 1.f / (1.f + __expf(-p));
    }
}

// ================================ launch ===================================
extern "C" void kernel_launch(void* const* d_in, const int* in_sizes, int n_in,
                              void* d_out, int out_size)
{
    const int*   u       = (const int*)d_in[0];
    const int*   v       = (const int*)d_in[1];
    const int*   adj_ent = (const int*)d_in[2];
    const int*   adj_rel = (const int*)d_in[3];
    const float* usr     = (const float*)d_in[4];
    const float* ent     = (const float*)d_in[5];
    const float* rel     = (const float*)d_in[6];
    const float* W       = (const float*)d_in[7];
    const float* bias    = (const float*)d_in[8];
    float* out = (float*)d_out;

    const int B = in_sizes[0];   // 8192

    static bool attr_set = false;
    if (!attr_set) {
        cudaFuncSetAttribute(gemm_kernel,
                             cudaFuncAttributeMaxDynamicSharedMemorySize,
                             SMEM_BYTES);
        attr_set = true;
    }

    dim3 g1((B + 7) / 8);                      // 1024 blocks, 1 warp/item
    gather_kernel<<<g1, 256>>>(u, v, adj_ent, adj_rel, usr, ent, rel, B);

    dim3 g2((B + ITEMS_PB - 1) / ITEMS_PB);    // 256 blocks, 2/SM, one wave
    gemm_kernel<<<g2, BLOCK_THREADS, SMEM_BYTES>>>(W, bias, out, B);
}

// round 17
// speedup vs baseline: 1.2561x; 1.2561x over previous
#include <cuda_runtime.h>
#include <cuda_bf16.h>
#include <cstdint>

#define D            128
#define S            16
#define NREL         64
#define ITEMS_PB     32
#define BLOCK_THREADS 512

#define HSTRIDE      136    // bf16 stride
#define FSTRIDE      132    // fp32 stride (Hs)
#define SCSTRIDE     68     // fp32 stride (SC)

// smem (bytes): Wt 34816 (aliased by Hs fp32 [32][132]) | Rt 17408 | SC 8704 |
//               Us 8704 | Xs 8704 | Ms 8704   => 87040 -> 2 blocks/SM (174KB)
#define OFF_WT  0
#define OFF_RT  34816
#define OFF_SC  (OFF_RT + 17408)
#define OFF_US  (OFF_SC + 8704)
#define OFF_XS  (OFF_US + 8704)
#define OFF_MS  (OFF_XS + 8704)
#define SMEM_BYTES (OFF_MS + 8704)

__device__ __forceinline__ void mma_bf16(float acc[4], const uint32_t a[4],
                                         const uint32_t b[2]) {
    asm("mma.sync.aligned.m16n8k16.row.col.f32.bf16.bf16.f32 "
        "{%0,%1,%2,%3}, {%4,%5,%6,%7}, {%8,%9}, {%0,%1,%2,%3};"
        : "+f"(acc[0]), "+f"(acc[1]), "+f"(acc[2]), "+f"(acc[3])
        : "r"(a[0]), "r"(a[1]), "r"(a[2]), "r"(a[3]),
          "r"(b[0]), "r"(b[1]));
}

__device__ __forceinline__ uint32_t pack_bf16x2(float lo, float hi) {
    __nv_bfloat162 v = __floats2bfloat162_rn(lo, hi);
    return *(uint32_t*)&v;
}

// named barrier for the 8 GEMM warps only (256 threads)
#define GEMM_BAR() asm volatile("bar.sync 5, 256;" ::: "memory")

__global__ __launch_bounds__(BLOCK_THREADS, 2)     // 32 warps/SM
void kgcn_kernel(const int* __restrict__ u,
                 const int* __restrict__ v,
                 const int* __restrict__ adj_ent,
                 const int* __restrict__ adj_rel,
                 const float* __restrict__ usr,
                 const float* __restrict__ ent,
                 const float* __restrict__ rel,
                 const float* __restrict__ W,
                 const float* __restrict__ bias,
                 float* __restrict__ out,
                 int B)
{
    extern __shared__ char sm[];
    __nv_bfloat16* Wt = (__nv_bfloat16*)(sm + OFF_WT);
    __nv_bfloat16* Rt = (__nv_bfloat16*)(sm + OFF_RT);
    float*         SC = (float*)        (sm + OFF_SC);
    __nv_bfloat16* Us = (__nv_bfloat16*)(sm + OFF_US);
    __nv_bfloat16* Xs = (__nv_bfloat16*)(sm + OFF_XS);
    __nv_bfloat16* Ms = (__nv_bfloat16*)(sm + OFF_MS);
    float*         Hs = (float*)        (sm + OFF_WT);   // aliases Wt

    const int tid  = threadIdx.x;
    const int lane = tid & 31;
    const int wid  = tid >> 5;
    const int g    = lane >> 2;
    const int tq   = lane & 3;
    const bool isGather = (wid < 8);
    const int  t2  = tid - 256;            // GEMM-warp-local thread id (0..255)

    const int base = blockIdx.x * ITEMS_PB;

    const float4* usr4 = (const float4*)usr;
    const float4* ent4 = (const float4*)ent;
    const int4*   adjE4 = (const int4*)adj_ent;
    const int4*   adjR4 = (const int4*)adj_rel;

    int iu_[4], iv_[4];

    // ---------------- P0: Us (gather warps) | Rt (GEMM warps) ----------------
    if (isGather) {
        #pragma unroll
        for (int t = 0; t < 4; t++) {
            const int item = base + wid * 4 + t;
            const int cit  = item < B ? item : (B - 1);
            iu_[t] = u[cit];
            iv_[t] = v[cit];
            const float4 uex = usr4[(size_t)iu_[t] * 32 + lane];
            const int row = wid * 4 + t;
            uint32_t* up = (uint32_t*)(Us + row * HSTRIDE + lane * 4);
            up[0] = pack_bf16x2(uex.x, uex.y);
            up[1] = pack_bf16x2(uex.z, uex.w);
        }
    } else {
        for (int i = t2; i < NREL * D; i += 256) {
            const int r = i >> 7;
            const int k = i & 127;
            Rt[r * HSTRIDE + k] = __float2bfloat16(rel[i]);
        }
    }
    __syncthreads();   // B_U

    // ---------------- P1: SC score GEMM (GEMM warps) --------------------------
    if (!isGather) {
        const int nc0 = (wid - 8) * 8;
        float sacc[2][4];
        #pragma unroll
        for (int mt = 0; mt < 2; mt++) {
            sacc[mt][0] = 0.f; sacc[mt][1] = 0.f;
            sacc[mt][2] = 0.f; sacc[mt][3] = 0.f;
        }
        #pragma unroll
        for (int kt = 0; kt < 8; kt++) {
            uint32_t b[2];
            const __nv_bfloat16* rb = Rt + (nc0 + g) * HSTRIDE + kt * 16 + tq * 2;
            b[0] = *(const uint32_t*)(rb);
            b[1] = *(const uint32_t*)(rb + 8);
            #pragma unroll
            for (int mt = 0; mt < 2; mt++) {
                uint32_t a[4];
                const __nv_bfloat16* xb = Us + (mt * 16 + g) * HSTRIDE + kt * 16 + tq * 2;
                a[0] = *(const uint32_t*)(xb);
                a[1] = *(const uint32_t*)(xb + 8 * HSTRIDE);
                a[2] = *(const uint32_t*)(xb + 8);
                a[3] = *(const uint32_t*)(xb + 8 * HSTRIDE + 8);
                mma_bf16(sacc[mt], a, b);
            }
        }
        #pragma unroll
        for (int mt = 0; mt < 2; mt++) {
            const int c0 = nc0 + tq * 2;
            const int r0 = mt * 16 + g;
            const int r1 = r0 + 8;
            *(float2*)(SC + r0 * SCSTRIDE + c0) = make_float2(sacc[mt][0], sacc[mt][1]);
            *(float2*)(SC + r1 * SCSTRIDE + c0) = make_float2(sacc[mt][2], sacc[mt][3]);
        }
    }
    __syncthreads();   // B_SC

    // ------- P2: gathers (gather warps)  ||  Wt staging (GEMM warps) ---------
    if (isGather) {
        #pragma unroll
        for (int t = 0; t < 4; t++) {
            const int iv  = iv_[t];
            const int row = wid * 4 + t;

            const float4 rp = ent4[(size_t)iv * 32 + lane];
            const float* scr = SC + row * SCSTRIDE;

            float sum = 0.f;
            float4 msg = make_float4(0.f, 0.f, 0.f, 0.f);
            #pragma unroll
            for (int q = 0; q < 4; q++) {
                const int4 ei = __ldg(&adjE4[iv * 4 + q]);
                const int4 ri = __ldg(&adjR4[iv * 4 + q]);
                const int es_[4] = {ei.x, ei.y, ei.z, ei.w};
                const int rs_[4] = {ri.x, ri.y, ri.z, ri.w};
                #pragma unroll
                for (int s = 0; s < 4; s++) {
                    const float4 e4 = ent4[(size_t)es_[s] * 32 + lane];
                    const float e = __expf(scr[rs_[s]]);   // |p| << 1, validated
                    sum += e;
                    msg.x = fmaf(e, e4.x, msg.x);
                    msg.y = fmaf(e, e4.y, msg.y);
                    msg.z = fmaf(e, e4.z, msg.z);
                    msg.w = fmaf(e, e4.w, msg.w);
                }
            }
            const float inv = __frcp_rn(sum);
            msg.x *= inv; msg.y *= inv; msg.z *= inv; msg.w *= inv;

            uint32_t* xp = (uint32_t*)(Xs + row * HSTRIDE + lane * 4);
            uint32_t* mp = (uint32_t*)(Ms + row * HSTRIDE + lane * 4);
            xp[0] = pack_bf16x2(msg.x + rp.x, msg.y + rp.y);
            xp[1] = pack_bf16x2(msg.z + rp.z, msg.w + rp.w);
            mp[0] = pack_bf16x2(msg.x, msg.y);
            mp[1] = pack_bf16x2(msg.z, msg.w);
        }
    } else {
        // Wt staging fully hidden under the gathers
        for (int i = t2; i < D * D; i += 256) {
            const int k = i >> 7;
            const int n = i & 127;
            Wt[n * HSTRIDE + k] = __float2bfloat16(W[i]);
        }
    }
    __syncthreads();   // B_X: Xs/Ms/Wt all ready

    // ---------------- P3: main GEMM (GEMM warps only, bar5-synced) ------------
    if (!isGather) {
        const int ncol0 = (wid - 8) * 16;
        float bb[2][2];
        #pragma unroll
        for (int nt = 0; nt < 2; nt++) {
            bb[nt][0] = __ldg(&bias[ncol0 + nt * 8 + tq * 2]);
            bb[nt][1] = __ldg(&bias[ncol0 + nt * 8 + tq * 2 + 1]);
        }

        float acc[2][2][4];
        #pragma unroll
        for (int iter = 0; iter < 2; iter++) {
            #pragma unroll
            for (int mt = 0; mt < 2; mt++)
                #pragma unroll
                for (int nt = 0; nt < 2; nt++) {
                    acc[mt][nt][0] = bb[nt][0]; acc[mt][nt][1] = bb[nt][1];
                    acc[mt][nt][2] = bb[nt][0]; acc[mt][nt][3] = bb[nt][1];
                }

            #pragma unroll
            for (int kt = 0; kt < 8; kt++) {
                uint32_t a[2][4];
                #pragma unroll
                for (int mt = 0; mt < 2; mt++) {
                    const __nv_bfloat16* xb = Xs + (mt * 16 + g) * HSTRIDE + kt * 16 + tq * 2;
                    a[mt][0] = *(const uint32_t*)(xb);
                    a[mt][1] = *(const uint32_t*)(xb + 8 * HSTRIDE);
                    a[mt][2] = *(const uint32_t*)(xb + 8);
                    a[mt][3] = *(const uint32_t*)(xb + 8 * HSTRIDE + 8);
                }
                uint32_t b[2][2];
                #pragma unroll
                for (int nt = 0; nt < 2; nt++) {
                    const __nv_bfloat16* wb = Wt + (ncol0 + nt * 8 + g) * HSTRIDE + kt * 16 + tq * 2;
                    b[nt][0] = *(const uint32_t*)(wb);
                    b[nt][1] = *(const uint32_t*)(wb + 8);
                }
                #pragma unroll
                for (int mt = 0; mt < 2; mt++)
                    #pragma unroll
                    for (int nt = 0; nt < 2; nt++)
                        mma_bf16(acc[mt][nt], a[mt], b[nt]);
            }

            GEMM_BAR();   // all GEMM warps' Xs/Wt reads done

            if (iter == 0) {
                #pragma unroll
                for (int mt = 0; mt < 2; mt++) {
                    #pragma unroll
                    for (int nt = 0; nt < 2; nt++) {
                        const int c0 = ncol0 + nt * 8 + tq * 2;
                        const int r0 = mt * 16 + g;
                        const int r1 = r0 + 8;
                        const float2 m0 = __bfloat1622float2(*(const __nv_bfloat162*)(Ms + r0 * HSTRIDE + c0));
                        const float2 m1 = __bfloat1622float2(*(const __nv_bfloat162*)(Ms + r1 * HSTRIDE + c0));
                        *(uint32_t*)(Xs + r0 * HSTRIDE + c0) =
                            pack_bf16x2(m0.x + fmaxf(acc[mt][nt][0], 0.f),
                                        m0.y + fmaxf(acc[mt][nt][1], 0.f));
                        *(uint32_t*)(Xs + r1 * HSTRIDE + c0) =
                            pack_bf16x2(m1.x + fmaxf(acc[mt][nt][2], 0.f),
                                        m1.y + fmaxf(acc[mt][nt][3], 0.f));
                    }
                }
                GEMM_BAR();   // rewrite complete before layer-2 reads
            }
        }

        // rep2 = relu(h2) -> Hs (aliases Wt; all Wt reads finished at last bar)
        #pragma unroll
        for (int mt = 0; mt < 2; mt++) {
            #pragma unroll
            for (int nt = 0; nt < 2; nt++) {
                const int c0 = ncol0 + nt * 8 + tq * 2;
                const int r0 = mt * 16 + g;
                const int r1 = r0 + 8;
                *(float2*)(Hs + r0 * FSTRIDE + c0) =
                    make_float2(fmaxf(acc[mt][nt][0], 0.f), fmaxf(acc[mt][nt][1], 0.f));
                *(float2*)(Hs + r1 * FSTRIDE + c0) =
                    make_float2(fmaxf(acc[mt][nt][2], 0.f), fmaxf(acc[mt][nt][3], 0.f));
            }
        }
    }
    __syncthreads();   // B_H: Hs ready

    // ---------------- P4: epilogue (gather warps) -----------------------------
    if (isGather) {
        #pragma unroll
        for (int t = 0; t < 4; t++) {
            const int item = base + wid * 4 + t;
            const int row  = wid * 4 + t;
            const float4 uex = usr4[(size_t)iu_[t] * 32 + lane];   // L2-hot
            const float4 h = *(const float4*)(Hs + row * FSTRIDE + lane * 4);
            float p = uex.x * h.x + uex.y * h.y + uex.z * h.z + uex.w * h.w;
            #pragma unroll
            for (int o = 16; o > 0; o >>= 1)
                p += __shfl_xor_sync(0xffffffffu, p, o);
            if (lane == 0 && item < B)
                out[item] = 1.f / (1.f + __expf(-p));
        }
    }
}

extern "C" void kernel_launch(void* const* d_in, const int* in_sizes, int n_in,
                              void* d_out, int out_size)
{
    const int*   u       = (const int*)d_in[0];
    const int*   v       = (const int*)d_in[1];
    const int*   adj_ent = (const int*)d_in[2];
    const int*   adj_rel = (const int*)d_in[3];
    const float* usr     = (const float*)d_in[4];
    const float* ent     = (const float*)d_in[5];
    const float* rel     = (const float*)d_in[6];
    const float* W       = (const float*)d_in[7];
    const float* bias    = (const float*)d_in[8];
    float* out = (float*)d_out;

    const int B = in_sizes[0];

    static bool attr_set = false;
    if (!attr_set) {
        cudaFuncSetAttribute(kgcn_kernel,
                             cudaFuncAttributeMaxDynamicSharedMemorySize,
                             SMEM_BYTES);
        attr_set = true;
    }

    dim3 grid((B + ITEMS_PB - 1) / ITEMS_PB);   // 256 blocks, 2/SM, 32 warps/SM
    kgcn_kernel<<<grid, BLOCK_THREADS, SMEM_BYTES>>>(
        u, v, adj_ent, adj_rel, usr, ent, rel, W, bias, out, B);
}